// round 5
// baseline (speedup 1.0000x reference)
#include <cuda_runtime.h>
#include <cuda_bf16.h>
#include <math.h>
#include <stdint.h>

#define Bd 128
#define Td 512
#define Ed 768
#define Hd 256
#define H4 1024
#define Ld 9
#define KP 2304    // packed K: [hi | lo | hi] x 768

// ---------------- device scratch (static, allowed) ----------------
__device__ float g_xw[2][Td][Bd][H4];
__device__ float g_h[2][Td + 1][Bd][Hd];
__device__ unsigned g_bar_count[8];
__device__ unsigned g_bar_gen[8];
__device__ __nv_bfloat16 g_Ap[Bd * Td][KP];      // packed X   (302 MB)
__device__ __nv_bfloat16 g_Bp[2][H4][KP];        // packed Wih (9.4 MB)

// ---------------- init ----------------
__global__ void init_kernel(float* out) {
    int idx = blockIdx.x * blockDim.x + threadIdx.x;
    const int n = Bd * Hd;
    if (idx < n) {
        ((float*)g_h[0][0])[idx] = 0.f;
        ((float*)g_h[1][Td])[idx] = 0.f;
    }
    if (idx < 8) {
        g_bar_count[idx] = 0u;
        g_bar_gen[idx] = 0u;
    }
    if (idx == 0) out[0] = 0.f;
}

// ---------------- helpers ----------------
__device__ __forceinline__ void split4(float4 v, uint32_t& h01, uint32_t& h23,
                                       uint32_t& l01, uint32_t& l23) {
    asm("cvt.rn.bf16x2.f32 %0, %1, %2;" : "=r"(h01) : "f"(v.y), "f"(v.x));
    asm("cvt.rn.bf16x2.f32 %0, %1, %2;" : "=r"(h23) : "f"(v.w), "f"(v.z));
    float r0 = v.x - __uint_as_float(h01 << 16);
    float r1 = v.y - __uint_as_float(h01 & 0xffff0000u);
    float r2 = v.z - __uint_as_float(h23 << 16);
    float r3 = v.w - __uint_as_float(h23 & 0xffff0000u);
    asm("cvt.rn.bf16x2.f32 %0, %1, %2;" : "=r"(l01) : "f"(r1), "f"(r0));
    asm("cvt.rn.bf16x2.f32 %0, %1, %2;" : "=r"(l23) : "f"(r3), "f"(r2));
}

__device__ __forceinline__ void ldsm4(uint32_t (&r)[4], uint32_t addr) {
    asm volatile("ldmatrix.sync.aligned.m8n8.x4.shared.b16 {%0,%1,%2,%3}, [%4];"
                 : "=r"(r[0]), "=r"(r[1]), "=r"(r[2]), "=r"(r[3]) : "r"(addr));
}
__device__ __forceinline__ void mma_bf16(float (&d)[4], const uint32_t (&a)[4],
                                         uint32_t b0, uint32_t b1) {
    asm volatile(
        "mma.sync.aligned.m16n8k16.row.col.f32.bf16.bf16.f32 "
        "{%0,%1,%2,%3}, {%4,%5,%6,%7}, {%8,%9}, {%0,%1,%2,%3};"
        : "+f"(d[0]), "+f"(d[1]), "+f"(d[2]), "+f"(d[3])
        : "r"(a[0]), "r"(a[1]), "r"(a[2]), "r"(a[3]), "r"(b0), "r"(b1));
}
__device__ __forceinline__ void cp16(uint32_t s, const void* g) {
    asm volatile("cp.async.cg.shared.global [%0], [%1], 16;" :: "r"(s), "l"(g));
}
#define CP_COMMIT() asm volatile("cp.async.commit_group;" ::: "memory")
#define CP_WAIT(n)  asm volatile("cp.async.wait_group %0;" :: "n"(n) : "memory")

// smem tile: 128 rows x 32 bf16 (64B rows, 4x16B chunks), XOR swizzle so any
// 8 consecutive rows at one chunk index hit 8 distinct 16B slots mod 128B.
#define SWZB(row, c) ((row) * 64 + ((((c) ^ (((row) >> 1) & 3))) << 4))

// ---------------- pack kernels ----------------
__global__ void pack_A(const float* __restrict__ X) {
    size_t i = (size_t)blockIdx.x * 256 + threadIdx.x;   // float4 index
    int m = (int)(i / 192);
    int kq = (int)(i % 192) * 4;
    float4 v = *(const float4*)(X + (size_t)m * Ed + kq);
    uint32_t h01, h23, l01, l23;
    split4(v, h01, h23, l01, l23);
    *(uint2*)&g_Ap[m][kq]        = make_uint2(h01, h23);
    *(uint2*)&g_Ap[m][768 + kq]  = make_uint2(l01, l23);
    *(uint2*)&g_Ap[m][1536 + kq] = make_uint2(h01, h23);
}

__global__ void pack_B(const float* __restrict__ Wf, const float* __restrict__ Wb) {
    const int dir = blockIdx.y;
    const float* W = dir ? Wb : Wf;
    int i = blockIdx.x * 256 + threadIdx.x;
    int n = i / 192;
    int kq = (i % 192) * 4;
    float4 v = *(const float4*)(W + (size_t)n * Ed + kq);
    uint32_t h01, h23, l01, l23;
    split4(v, h01, h23, l01, l23);
    *(uint2*)&g_Bp[dir][n][kq]        = make_uint2(h01, h23);
    *(uint2*)&g_Bp[dir][n][768 + kq]  = make_uint2(h01, h23);
    *(uint2*)&g_Bp[dir][n][1536 + kq] = make_uint2(l01, l23);
}

// ---------------- input GEMM: pure bf16 over packed K'=2304 ----------------
// C = A'·B'^T = AhiBhi + AloBhi + AhiBlo (== bf16x3 emulated fp32).
// CTA 128m x 128n, 8 warps (4m x 2n), 4-stage cp.async pipeline, k32 chunks.
#define G_SMEM (4 * 16384)

__global__ void __launch_bounds__(256, 1)
gemm_xw_pk(const float* __restrict__ bihf, const float* __restrict__ bhhf,
           const float* __restrict__ bihb, const float* __restrict__ bhhb) {
    extern __shared__ char smem[];
    const uint32_t sb = (uint32_t)__cvta_generic_to_shared(smem);

    const int dir = blockIdx.z;
    const float* __restrict__ bih = dir ? bihb : bihf;
    const float* __restrict__ bhh = dir ? bhhb : bhhf;

    const int n0 = blockIdx.x * 128;
    const int m0 = blockIdx.y * 128;
    const int tid = threadIdx.x;
    const int warp = tid >> 5;
    const int lane = tid & 31;
    const int wm = (warp >> 1) << 5;   // 0,32,64,96
    const int wn = (warp & 1) << 6;    // 0,64

    // cp.async coords: 2 chunks of A + 2 of B per thread per stage
    const int r0_ = tid >> 2,        c0_ = tid & 3;          // rows 0..63
    const int r1_ = (tid + 256) >> 2, c1_ = tid & 3;         // rows 64..127
    const uint32_t sA0 = SWZB(r0_, c0_), sA1 = SWZB(r1_, c1_);
    const __nv_bfloat16* Abase = &g_Ap[m0][0];
    const __nv_bfloat16* Bbase = &g_Bp[dir][n0][0];
    const size_t a0off = (size_t)r0_ * KP + c0_ * 8;
    const size_t a1off = (size_t)r1_ * KP + c1_ * 8;

#define ISSUE(stg, k0) do {                                             \
        uint32_t _st = sb + ((stg) & 3) * 16384;                        \
        cp16(_st + sA0,        Abase + a0off + (k0));                   \
        cp16(_st + sA1,        Abase + a1off + (k0));                   \
        cp16(_st + 8192 + sA0, Bbase + a0off + (k0));                   \
        cp16(_st + 8192 + sA1, Bbase + a1off + (k0));                   \
        CP_COMMIT();                                                    \
    } while (0)

    ISSUE(0, 0);
    ISSUE(1, 32);
    ISSUE(2, 64);

    float acc[2][8][4];
#pragma unroll
    for (int i = 0; i < 2; i++)
#pragma unroll
        for (int j = 0; j < 8; j++)
#pragma unroll
            for (int q = 0; q < 4; q++) acc[i][j][q] = 0.f;

    // hoisted fragment address pieces
    const int arow_l = lane & 15;
    const int ac_l   = lane >> 4;              // 0/1
    const int brow_l = ((lane >> 4) << 3) + (lane & 7);
    const int bc_l   = (lane >> 3) & 1;

    const int NIT = KP / 32;   // 72
#pragma unroll 1
    for (int kt = 0; kt < NIT; kt++) {
        if (kt < NIT - 2)      { CP_WAIT(2); }
        else if (kt == NIT - 2){ CP_WAIT(1); }
        else                   { CP_WAIT(0); }
        __syncthreads();
        if (kt + 3 < NIT) ISSUE(kt + 3, (kt + 3) * 32);

        const uint32_t stA = sb + (kt & 3) * 16384;
        const uint32_t stB = stA + 8192;
#pragma unroll
        for (int ks = 0; ks < 2; ks++) {
            uint32_t a[2][4];
            const int ac = ks * 2 + ac_l;
#pragma unroll
            for (int i = 0; i < 2; i++) {
                int row = wm + i * 16 + arow_l;
                ldsm4(a[i], stA + SWZB(row, ac));
            }
            const int bc = ks * 2 + bc_l;
#pragma unroll
            for (int g = 0; g < 4; g++) {
                uint32_t b[4];
                int row = wn + g * 16 + brow_l;
                ldsm4(b, stB + SWZB(row, bc));
#pragma unroll
                for (int i = 0; i < 2; i++) {
                    mma_bf16(acc[i][2 * g],     a[i], b[0], b[1]);
                    mma_bf16(acc[i][2 * g + 1], a[i], b[2], b[3]);
                }
            }
        }
    }
#undef ISSUE

    // epilogue: add bias, scatter to g_xw[dir][t][b][n]
    const int lr = lane >> 2;
    const int lc = (lane & 3) * 2;
#pragma unroll
    for (int j = 0; j < 8; j++) {
        const int n = n0 + wn + j * 8 + lc;
        const float b0 = bih[n] + bhh[n];
        const float b1 = bih[n + 1] + bhh[n + 1];
#pragma unroll
        for (int i = 0; i < 2; i++) {
            int m = m0 + wm + i * 16 + lr;
            int bb = m >> 9, t = m & 511;
            *(float2*)&g_xw[dir][t][bb][n] =
                make_float2(acc[i][j][0] + b0, acc[i][j][1] + b1);
            m += 8; bb = m >> 9; t = m & 511;
            *(float2*)&g_xw[dir][t][bb][n] =
                make_float2(acc[i][j][2] + b0, acc[i][j][3] + b1);
        }
    }
}

// ---------------- persistent LSTM recurrence (unchanged, proven) ----------------
#define REC_SMEM_FLOATS (64 * 260 + 32 * 260 + 512)

__device__ __forceinline__ float sigmoidf_fast(float x) {
    return 1.f / (1.f + __expf(-x));
}

__global__ void lstm_rec(const float* __restrict__ Whhf, const float* __restrict__ Whhb) {
    extern __shared__ float sm[];
    float* Ws = sm;
    float* hs = sm + 64 * 260;
    float* cs = hs + 32 * 260;

    const int tid = threadIdx.x;
    const int dir = blockIdx.x >> 6;
    const int c   = blockIdx.x & 63;
    const int bt  = c >> 4;
    const int b0  = bt * 32;
    const int j0  = (c & 15) * 16;
    const int grp = (dir << 2) | bt;

    const float* Whh = dir ? Whhb : Whhf;

    for (int idx = tid; idx < 64 * 64; idx += 256) {
        int r  = idx >> 6;
        int k4 = (idx & 63) * 4;
        int g  = r >> 4, jj = r & 15;
        float4 v = *(const float4*)&Whh[(size_t)(g * Hd + j0 + jj) * Hd + k4];
        *(float4*)&Ws[r * 260 + k4] = v;
    }
    for (int idx = tid; idx < 512; idx += 256) cs[idx] = 0.f;

    const int b_l = tid >> 3;
    const int jj  = tid & 7;
    __syncthreads();

    for (int s = 0; s < Td; s++) {
        const int t     = dir ? (Td - 1 - s) : s;
        const int rslot = dir ? (t + 1) : t;
        const int wslot = dir ? t : (t + 1);

        const float* hsrc = &g_h[dir][rslot][b0][0];
        for (int idx = tid; idx < 32 * 64; idx += 256) {
            int bb = idx >> 6;
            int k4 = (idx & 63) * 4;
            float4 v = __ldcg((const float4*)(hsrc + bb * Hd + k4));
            *(float4*)&hs[bb * 260 + k4] = v;
        }
        __syncthreads();

        const float* xw = &g_xw[dir][t][b0 + b_l][0];
        float acc0[4], acc1[4];
#pragma unroll
        for (int g = 0; g < 4; g++) {
            acc0[g] = xw[g * Hd + j0 + jj];
            acc1[g] = xw[g * Hd + j0 + jj + 8];
        }
        const float* hp = &hs[b_l * 260];
#pragma unroll 8
        for (int k = 0; k < Hd; k += 4) {
            float4 hv = *(const float4*)(hp + k);
#pragma unroll
            for (int g = 0; g < 4; g++) {
                float4 w0 = *(const float4*)&Ws[(g * 16 + jj) * 260 + k];
                float4 w1 = *(const float4*)&Ws[(g * 16 + jj + 8) * 260 + k];
                acc0[g] += hv.x * w0.x + hv.y * w0.y + hv.z * w0.z + hv.w * w0.w;
                acc1[g] += hv.x * w1.x + hv.y * w1.y + hv.z * w1.z + hv.w * w1.w;
            }
        }

        float c0 = cs[jj * 32 + b_l];
        float c1 = cs[(jj + 8) * 32 + b_l];
        float i0 = sigmoidf_fast(acc0[0]);
        float f0 = sigmoidf_fast(acc0[1]);
        float g0 = tanhf(acc0[2]);
        float o0 = sigmoidf_fast(acc0[3]);
        c0 = f0 * c0 + i0 * g0;
        float h0 = o0 * tanhf(c0);
        float i1 = sigmoidf_fast(acc1[0]);
        float f1 = sigmoidf_fast(acc1[1]);
        float g1 = tanhf(acc1[2]);
        float o1 = sigmoidf_fast(acc1[3]);
        c1 = f1 * c1 + i1 * g1;
        float h1 = o1 * tanhf(c1);
        cs[jj * 32 + b_l] = c0;
        cs[(jj + 8) * 32 + b_l] = c1;

        float* hdst = &g_h[dir][wslot][b0 + b_l][j0];
        hdst[jj]     = h0;
        hdst[jj + 8] = h1;

        __threadfence();
        __syncthreads();
        if (tid == 0) {
            unsigned arr = atomicAdd(&g_bar_count[grp], 1u);
            if (arr == 15u) {
                g_bar_count[grp] = 0u;
                __threadfence();
                atomicAdd(&g_bar_gen[grp], 1u);
            } else {
                while (*((volatile unsigned*)&g_bar_gen[grp]) < (unsigned)(s + 1))
                    __nanosleep(64);
                __threadfence();
            }
        }
        __syncthreads();
    }
}

// ---------------- emissions + CRF NLL (unchanged, proven) ----------------
__global__ void emis_crf(const int* __restrict__ mask, const int* __restrict__ labels32,
                         const float* __restrict__ Wout, const float* __restrict__ bout,
                         const float* __restrict__ start_t, const float* __restrict__ end_t,
                         const float* __restrict__ trans, float* out) {
    __shared__ float Wsm[Ld * 2 * Hd];
    __shared__ float em[Td * Ld];
    __shared__ float tr[Ld * Ld];
    __shared__ int msk[Td];
    __shared__ int lab[Td];
    __shared__ int lab_is64;
    __shared__ float score_sm;
    __shared__ float logZ_sm;

    const int b = blockIdx.x;
    const int tid = threadIdx.x;

    if (tid == 0) {
        int odd_or = 0;
        for (int i = 1; i < 128; i += 2) odd_or |= labels32[i];
        lab_is64 = (odd_or == 0) ? 1 : 0;
    }
    for (int i = tid; i < Ld * 2 * Hd; i += blockDim.x) Wsm[i] = Wout[i];
    for (int i = tid; i < Td; i += blockDim.x) msk[i] = mask[(size_t)b * Td + i];
    for (int i = tid; i < Ld * Ld; i += blockDim.x) tr[i] = trans[i];
    __syncthreads();
    const int stride = lab_is64 ? 2 : 1;
    for (int i = tid; i < Td; i += blockDim.x)
        lab[i] = labels32[((size_t)b * Td + i) * stride];
    __syncthreads();

    const int w = tid >> 5, lane = tid & 31;
    for (int t = w; t < Td; t += 8) {
        float p[Ld];
#pragma unroll
        for (int l = 0; l < Ld; l++) p[l] = 0.f;
        const float* hf = &g_h[0][t + 1][b][0];
        const float* hb = &g_h[1][t][b][0];
#pragma unroll
        for (int kk = 0; kk < 8; kk++) {
            int k = kk * 32 + lane;
            float hv = hf[k];
#pragma unroll
            for (int l = 0; l < Ld; l++) p[l] += hv * Wsm[l * 512 + k];
        }
#pragma unroll
        for (int kk = 0; kk < 8; kk++) {
            int k = kk * 32 + lane;
            float hv = hb[k];
#pragma unroll
            for (int l = 0; l < Ld; l++) p[l] += hv * Wsm[l * 512 + 256 + k];
        }
#pragma unroll
        for (int l = 0; l < Ld; l++) {
            float v = p[l];
#pragma unroll
            for (int off = 16; off; off >>= 1) v += __shfl_down_sync(0xffffffffu, v, off);
            if (lane == 0) em[t * Ld + l] = v + bout[l];
        }
    }
    __syncthreads();

    if (tid == 32) {
        int prev = lab[0];
        float sc = start_t[prev] + em[0 * Ld + prev];
        for (int t = 1; t < Td; t++) {
            if (msk[t]) {
                int cur = lab[t];
                sc += em[t * Ld + cur] + tr[prev * Ld + cur];
                prev = cur;
            }
        }
        sc += end_t[prev];
        score_sm = sc;
    }

    if (tid < 32) {
        const int j = lane;
        const bool act = j < Ld;
        float tcol[Ld];
#pragma unroll
        for (int i = 0; i < Ld; i++) tcol[i] = act ? tr[i * Ld + j] : 0.f;
        float alpha = act ? (start_t[j] + em[0 * Ld + j]) : -1e30f;
        for (int t = 1; t < Td; t++) {
            float vv[Ld];
            float mx = -1e30f;
#pragma unroll
            for (int i = 0; i < Ld; i++) {
                float ai = __shfl_sync(0xffffffffu, alpha, i);
                vv[i] = ai + tcol[i];
                mx = fmaxf(mx, vv[i]);
            }
            float ssum = 0.f;
#pragma unroll
            for (int i = 0; i < Ld; i++) ssum += __expf(vv[i] - mx);
            float nxt = mx + __logf(ssum) + (act ? em[t * Ld + j] : 0.f);
            if (msk[t]) alpha = nxt;
        }
        float v = act ? (alpha + end_t[j]) : -1e30f;
        float mx = v;
#pragma unroll
        for (int off = 16; off; off >>= 1) mx = fmaxf(mx, __shfl_xor_sync(0xffffffffu, mx, off));
        float s = __expf(v - mx);
#pragma unroll
        for (int off = 16; off; off >>= 1) s += __shfl_xor_sync(0xffffffffu, s, off);
        if (lane == 0) logZ_sm = mx + __logf(s);
    }
    __syncthreads();
    if (tid == 0) atomicAdd(out, logZ_sm - score_sm);
}

// ---------------- launch ----------------
extern "C" void kernel_launch(void* const* d_in, const int* in_sizes, int n_in,
                              void* d_out, int out_size) {
    const float* X      = (const float*)d_in[0];
    const int*   mask   = (const int*)d_in[1];
    const int*   labels = (const int*)d_in[2];
    const float* Wih_f = (const float*)d_in[3];
    const float* Whh_f = (const float*)d_in[4];
    const float* bih_f = (const float*)d_in[5];
    const float* bhh_f = (const float*)d_in[6];
    const float* Wih_b = (const float*)d_in[7];
    const float* Whh_b = (const float*)d_in[8];
    const float* bih_b = (const float*)d_in[9];
    const float* bhh_b = (const float*)d_in[10];
    const float* W_out = (const float*)d_in[11];
    const float* b_out = (const float*)d_in[12];
    const float* start_t = (const float*)d_in[13];
    const float* end_t   = (const float*)d_in[14];
    const float* trans   = (const float*)d_in[15];
    float* out = (float*)d_out;

    const int rec_smem = REC_SMEM_FLOATS * (int)sizeof(float);
    cudaFuncSetAttribute(lstm_rec, cudaFuncAttributeMaxDynamicSharedMemorySize, rec_smem);
    cudaFuncSetAttribute(gemm_xw_pk, cudaFuncAttributeMaxDynamicSharedMemorySize, G_SMEM);

    init_kernel<<<128, 256>>>(out);
    pack_A<<<(Bd * Td * Ed / 4) / 256, 256>>>(X);
    pack_B<<<dim3((H4 * Ed / 4) / 256, 2), 256>>>(Wih_f, Wih_b);
    gemm_xw_pk<<<dim3(8, 512, 2), 256, G_SMEM>>>(bih_f, bhh_f, bih_b, bhh_b);
    lstm_rec<<<128, 256, rec_smem>>>(Whh_f, Whh_b);
    emis_crf<<<128, 256>>>(mask, labels, W_out, b_out, start_t, end_t, trans, out);
}

// round 6
// speedup vs baseline: 1.2301x; 1.2301x over previous
#include <cuda_runtime.h>
#include <cuda_bf16.h>
#include <math.h>
#include <stdint.h>

#define Bd 128
#define Td 512
#define Ed 768
#define Hd 256
#define H4 1024
#define Ld 9

// ---------------- device scratch (static, allowed) ----------------
__device__ float g_xw[2][Td][Bd][H4];                       // 536 MB
__device__ __nv_bfloat16 g_hb[2][Td + 1][2][Bd][Hd];        // h hi/lo planes, 134 MB
__device__ unsigned g_bar_count[8];
__device__ unsigned g_bar_gen[8];

// ---------------- init ----------------
__global__ void init_kernel(float* out) {
    int idx = blockIdx.x * blockDim.x + threadIdx.x;   // 32768 threads
    ((uint32_t*)g_hb[0][0])[idx] = 0u;                 // fwd h(-1) = 0 (both planes)
    ((uint32_t*)g_hb[1][Td])[idx] = 0u;                // bwd h(T) = 0
    if (idx < 8) {
        g_bar_count[idx] = 0u;
        g_bar_gen[idx] = 0u;
    }
    if (idx == 0) out[0] = 0.f;
}

// ---------------- mma helpers ----------------
__device__ __forceinline__ void ldsm4(uint32_t (&r)[4], uint32_t addr) {
    asm volatile("ldmatrix.sync.aligned.m8n8.x4.shared.b16 {%0,%1,%2,%3}, [%4];"
                 : "=r"(r[0]), "=r"(r[1]), "=r"(r[2]), "=r"(r[3]) : "r"(addr));
}
__device__ __forceinline__ void mma_bf16(float (&d)[4], const uint32_t (&a)[4],
                                         uint32_t b0, uint32_t b1) {
    asm volatile(
        "mma.sync.aligned.m16n8k16.row.col.f32.bf16.bf16.f32 "
        "{%0,%1,%2,%3}, {%4,%5,%6,%7}, {%8,%9}, {%0,%1,%2,%3};"
        : "+f"(d[0]), "+f"(d[1]), "+f"(d[2]), "+f"(d[3])
        : "r"(a[0]), "r"(a[1]), "r"(a[2]), "r"(a[3]), "r"(b0), "r"(b1));
}
__device__ __forceinline__ void split4(float4 v, uint32_t& h01, uint32_t& h23,
                                       uint32_t& l01, uint32_t& l23) {
    asm("cvt.rn.bf16x2.f32 %0, %1, %2;" : "=r"(h01) : "f"(v.y), "f"(v.x));
    asm("cvt.rn.bf16x2.f32 %0, %1, %2;" : "=r"(h23) : "f"(v.w), "f"(v.z));
    float r0 = v.x - __uint_as_float(h01 << 16);
    float r1 = v.y - __uint_as_float(h01 & 0xffff0000u);
    float r2 = v.z - __uint_as_float(h23 << 16);
    float r3 = v.w - __uint_as_float(h23 & 0xffff0000u);
    asm("cvt.rn.bf16x2.f32 %0, %1, %2;" : "=r"(l01) : "f"(r1), "f"(r0));
    asm("cvt.rn.bf16x2.f32 %0, %1, %2;" : "=r"(l23) : "f"(r3), "f"(r2));
}
__device__ __forceinline__ void cvt_split_store(float4 v, __nv_bfloat16* hi, __nv_bfloat16* lo) {
    uint32_t h01, h23, l01, l23;
    split4(v, h01, h23, l01, l23);
    *(uint2*)hi = make_uint2(h01, h23);
    *(uint2*)lo = make_uint2(l01, l23);
}
__device__ __forceinline__ void cp16(uint32_t s, const void* g) {
    asm volatile("cp.async.cg.shared.global [%0], [%1], 16;" :: "r"(s), "l"(g));
}
#define CP_COMMIT() asm volatile("cp.async.commit_group;" ::: "memory")
#define CP_WAIT0()  asm volatile("cp.async.wait_group 0;" :: : "memory")

// ---------------- input GEMM (R3 version: mma.sync, inline bf16x3 split) ----------------
#define GSTG 20480           // bf16 elements per stage
#define GPLN 5120            // bf16 elements per plane (128*40)

__global__ void __launch_bounds__(256, 1)
gemm_xw_tc(const float* __restrict__ X,
           const float* __restrict__ Wf, const float* __restrict__ Wb,
           const float* __restrict__ bihf, const float* __restrict__ bhhf,
           const float* __restrict__ bihb, const float* __restrict__ bhhb) {
    extern __shared__ __nv_bfloat16 smbf[];

    const int dir = blockIdx.z;
    const float* __restrict__ W   = dir ? Wb   : Wf;
    const float* __restrict__ bih = dir ? bihb : bihf;
    const float* __restrict__ bhh = dir ? bhhb : bhhf;

    const int m0 = blockIdx.y * 128;
    const int n0 = blockIdx.x * 128;
    const int tid = threadIdx.x;
    const int lane = tid & 31;
    const int warp = tid >> 5;
    const int wm = (warp >> 1) << 5;
    const int wn = (warp & 1) << 6;

    const uint32_t smem_base = (uint32_t)__cvta_generic_to_shared(smbf);

    int lrow[4], lcol[4];
    const float *Ag[4], *Bg[4];
#pragma unroll
    for (int i = 0; i < 4; i++) {
        int idx = tid + i * 256;
        lrow[i] = idx >> 3;
        lcol[i] = (idx & 7) * 4;
        Ag[i] = X + (size_t)(m0 + lrow[i]) * Ed + lcol[i];
        Bg[i] = W + (size_t)(n0 + lrow[i]) * Ed + lcol[i];
    }

    float4 ra[4], rb[4];
#pragma unroll
    for (int i = 0; i < 4; i++) {
        ra[i] = *(const float4*)(Ag[i]);
        rb[i] = *(const float4*)(Bg[i]);
    }
#pragma unroll
    for (int i = 0; i < 4; i++) {
        int off = lrow[i] * 40 + lcol[i];
        cvt_split_store(ra[i], &smbf[off], &smbf[off + GPLN]);
        cvt_split_store(rb[i], &smbf[off + 2 * GPLN], &smbf[off + 3 * GPLN]);
    }
    __syncthreads();

    float acc[2][8][4];
#pragma unroll
    for (int i = 0; i < 2; i++)
#pragma unroll
        for (int j = 0; j < 8; j++)
#pragma unroll
            for (int q = 0; q < 4; q++) acc[i][j][q] = 0.f;

    int stage = 0;
#pragma unroll 1
    for (int k0 = 0; k0 < Ed; k0 += 32) {
        const bool more = (k0 + 32) < Ed;
        if (more) {
#pragma unroll
            for (int i = 0; i < 4; i++) {
                ra[i] = *(const float4*)(Ag[i] + k0 + 32);
                rb[i] = *(const float4*)(Bg[i] + k0 + 32);
            }
        }

        const uint32_t so = stage * GSTG;
#pragma unroll
        for (int ks = 0; ks < 32; ks += 16) {
            uint32_t ah[2][4], al[2][4];
            const int arow = lane & 15;
            const int acol = ks + ((lane >> 4) << 3);
#pragma unroll
            for (int i = 0; i < 2; i++) {
                uint32_t aoff = so + (uint32_t)((wm + i * 16 + arow) * 40 + acol);
                ldsm4(ah[i], smem_base + aoff * 2);
                ldsm4(al[i], smem_base + (aoff + GPLN) * 2);
            }
            const int brow = ((lane >> 4) << 3) + (lane & 7);
            const int bcol = ks + (((lane >> 3) & 1) << 3);
#pragma unroll
            for (int g = 0; g < 4; g++) {
                uint32_t boff = so + 2 * GPLN + (uint32_t)((wn + g * 16 + brow) * 40 + bcol);
                uint32_t bh[4], bl[4];
                ldsm4(bh, smem_base + boff * 2);
                ldsm4(bl, smem_base + (boff + GPLN) * 2);
#pragma unroll
                for (int i = 0; i < 2; i++) {
                    mma_bf16(acc[i][2 * g],     ah[i], bh[0], bh[1]);
                    mma_bf16(acc[i][2 * g],     ah[i], bl[0], bl[1]);
                    mma_bf16(acc[i][2 * g],     al[i], bh[0], bh[1]);
                    mma_bf16(acc[i][2 * g + 1], ah[i], bh[2], bh[3]);
                    mma_bf16(acc[i][2 * g + 1], ah[i], bl[2], bl[3]);
                    mma_bf16(acc[i][2 * g + 1], al[i], bh[2], bh[3]);
                }
            }
        }

        if (more) {
            const int ns = stage ^ 1;
#pragma unroll
            for (int i = 0; i < 4; i++) {
                int off = ns * GSTG + lrow[i] * 40 + lcol[i];
                cvt_split_store(ra[i], &smbf[off], &smbf[off + GPLN]);
                cvt_split_store(rb[i], &smbf[off + 2 * GPLN], &smbf[off + 3 * GPLN]);
            }
            __syncthreads();
            stage = ns;
        }
    }

    const int lr = lane >> 2;
    const int lc = (lane & 3) * 2;
#pragma unroll
    for (int j = 0; j < 8; j++) {
        const int n = n0 + wn + j * 8 + lc;
        const float b0 = bih[n] + bhh[n];
        const float b1 = bih[n + 1] + bhh[n + 1];
#pragma unroll
        for (int i = 0; i < 2; i++) {
            int m = m0 + wm + i * 16 + lr;
            int bb = m >> 9, t = m & 511;
            *(float2*)&g_xw[dir][t][bb][n] =
                make_float2(acc[i][j][0] + b0, acc[i][j][1] + b1);
            m += 8; bb = m >> 9; t = m & 511;
            *(float2*)&g_xw[dir][t][bb][n] =
                make_float2(acc[i][j][2] + b0, acc[i][j][3] + b1);
        }
    }
}

// ---------------- tensor-core LSTM recurrence ----------------
// 32 CTAs = 2 dirs x 16 j-slices. CTA: M=128(batch) x N=64(4g x 16j) x K=256.
// Whh hi/lo in smem (persistent); h exchanged as bf16 hi/lo planes via gmem.
// Warp w owns m-tile w (16 batches); thread holds all 4 gates of its (b,j) cells.
#define RST 528              // smem row stride bytes (264 bf16) - conflict-free ldsm
#define WHI_OFF 0
#define WLO_OFF (64 * RST)           // 33792
#define HHI_OFF (2 * 64 * RST)       // 67584
#define HLO_OFF (2 * 64 * RST + 128 * RST)
#define REC_SMEM (2 * 64 * RST + 2 * 128 * RST)   // 202752

__device__ __forceinline__ float sigf(float x) { return 1.f / (1.f + __expf(-x)); }

__global__ void __launch_bounds__(256, 1)
lstm_rec_mma(const float* __restrict__ Whhf, const float* __restrict__ Whhb) {
    extern __shared__ char rsm[];
    const uint32_t sb = (uint32_t)__cvta_generic_to_shared(rsm);

    const int tid  = threadIdx.x;
    const int warp = tid >> 5;
    const int lane = tid & 31;
    const int dir  = blockIdx.x >> 4;
    const int j0   = (blockIdx.x & 15) * 16;
    const int grp  = dir;

    const float* __restrict__ Whh = dir ? Whhb : Whhf;

    // load + split Whh rows (g*16+jj ordering), 64 x 256
#pragma unroll
    for (int i = 0; i < 16; i++) {
        int idx = tid + i * 256;
        int r = idx >> 6;
        int k4 = (idx & 63) * 4;
        int g = r >> 4, jj = r & 15;
        float4 v = *(const float4*)&Whh[(size_t)(g * Hd + j0 + jj) * Hd + k4];
        uint32_t h01, h23, l01, l23;
        split4(v, h01, h23, l01, l23);
        uint32_t off = (uint32_t)(r * RST + k4 * 2);
        asm volatile("st.shared.v2.b32 [%0], {%1,%2};"
                     :: "r"(sb + WHI_OFF + off), "r"(h01), "r"(h23) : "memory");
        asm volatile("st.shared.v2.b32 [%0], {%1,%2};"
                     :: "r"(sb + WLO_OFF + off), "r"(l01), "r"(l23) : "memory");
    }
    __syncthreads();

    // thread geometry
    const int lr = lane >> 2;
    const int c0 = (lane & 3) * 2;
    const int b0 = warp * 16 + lr;                       // batches b0, b0+8
    const int arow = warp * 16 + (lane & 15);
    const int ac_l = lane >> 4;
    const int brow = ((lane >> 4) << 3) + (lane & 7);
    const int bc_l = (lane >> 3) & 1;

    float cst[8];
#pragma unroll
    for (int i = 0; i < 8; i++) cst[i] = 0.f;

#pragma unroll 1
    for (int s = 0; s < Td; s++) {
        const int t     = dir ? (Td - 1 - s) : s;
        const int rslot = dir ? (t + 1) : t;
        const int wslot = dir ? t : (t + 1);

        // acc init = xw (bias already folded by GEMM)
        float acc[8][4];
#pragma unroll
        for (int nt = 0; nt < 8; nt++) {
            int g = nt >> 1;
            int jc = g * Hd + j0 + (nt & 1) * 8 + c0;
            float2 va = *(const float2*)&g_xw[dir][t][b0][jc];
            float2 vb = *(const float2*)&g_xw[dir][t][b0 + 8][jc];
            acc[nt][0] = va.x; acc[nt][1] = va.y;
            acc[nt][2] = vb.x; acc[nt][3] = vb.y;
        }

        // cp.async previous h (hi/lo planes) -> smem
        const char* hi_src = (const char*)&g_hb[dir][rslot][0][0][0];
        const char* lo_src = (const char*)&g_hb[dir][rslot][1][0][0];
#pragma unroll
        for (int i = 0; i < 16; i++) {
            int idx = tid + i * 256;
            int row = idx >> 5, ch = idx & 31;
            uint32_t d = (uint32_t)(row * RST + ch * 16);
            int srcoff = row * 512 + ch * 16;
            cp16(sb + HHI_OFF + d, hi_src + srcoff);
            cp16(sb + HLO_OFF + d, lo_src + srcoff);
        }
        CP_COMMIT();
        CP_WAIT0();
        __syncthreads();

        // z += h @ Whh^T  (bf16x3)
#pragma unroll
        for (int ks = 0; ks < 16; ks++) {
            uint32_t ah[4], al[4];
            uint32_t aaddr = sb + HHI_OFF + (uint32_t)(arow * RST + (ks * 2 + ac_l) * 16);
            ldsm4(ah, aaddr);
            ldsm4(al, aaddr + (HLO_OFF - HHI_OFF));
#pragma unroll
            for (int g2 = 0; g2 < 4; g2++) {
                uint32_t bh[4], bl[4];
                uint32_t baddr = sb + WHI_OFF +
                    (uint32_t)((g2 * 16 + brow) * RST + (ks * 2 + bc_l) * 16);
                ldsm4(bh, baddr);
                ldsm4(bl, baddr + WLO_OFF);
                mma_bf16(acc[2 * g2],     ah, bh[0], bh[1]);
                mma_bf16(acc[2 * g2],     al, bh[0], bh[1]);
                mma_bf16(acc[2 * g2],     ah, bl[0], bl[1]);
                mma_bf16(acc[2 * g2 + 1], ah, bh[2], bh[3]);
                mma_bf16(acc[2 * g2 + 1], al, bh[2], bh[3]);
                mma_bf16(acc[2 * g2 + 1], ah, bl[2], bl[3]);
            }
        }

        // gates -> c,h ; write h as bf16 hi/lo planes
#pragma unroll
        for (int m = 0; m < 2; m++) {
            const int b = b0 + m * 8;
#pragma unroll
            for (int jh = 0; jh < 2; jh++) {
                float hv[2];
#pragma unroll
                for (int c = 0; c < 2; c++) {
                    int q = m * 2 + c;
                    float iv = acc[jh + 0][q];
                    float fv = acc[jh + 2][q];
                    float gv = acc[jh + 4][q];
                    float ov = acc[jh + 6][q];
                    float cc = cst[m * 4 + jh * 2 + c];
                    cc = sigf(fv) * cc + sigf(iv) * tanhf(gv);
                    cst[m * 4 + jh * 2 + c] = cc;
                    hv[c] = sigf(ov) * tanhf(cc);
                }
                uint32_t h2, l2;
                asm("cvt.rn.bf16x2.f32 %0, %1, %2;" : "=r"(h2) : "f"(hv[1]), "f"(hv[0]));
                float r0 = hv[0] - __uint_as_float(h2 << 16);
                float r1 = hv[1] - __uint_as_float(h2 & 0xffff0000u);
                asm("cvt.rn.bf16x2.f32 %0, %1, %2;" : "=r"(l2) : "f"(r1), "f"(r0));
                const int jc = j0 + jh * 8 + c0;
                *(uint32_t*)&g_hb[dir][wslot][0][b][jc] = h2;
                *(uint32_t*)&g_hb[dir][wslot][1][b][jc] = l2;
            }
        }

        // 16-CTA group barrier (per dir)
        __threadfence();
        __syncthreads();
        if (tid == 0) {
            unsigned arr = atomicAdd(&g_bar_count[grp], 1u);
            if (arr == 15u) {
                g_bar_count[grp] = 0u;
                __threadfence();
                atomicAdd(&g_bar_gen[grp], 1u);
            } else {
                while (*((volatile unsigned*)&g_bar_gen[grp]) < (unsigned)(s + 1))
                    __nanosleep(64);
                __threadfence();
            }
        }
        __syncthreads();
    }
}

// ---------------- emissions + CRF NLL ----------------
__global__ void emis_crf(const int* __restrict__ mask, const int* __restrict__ labels32,
                         const float* __restrict__ Wout, const float* __restrict__ bout,
                         const float* __restrict__ start_t, const float* __restrict__ end_t,
                         const float* __restrict__ trans, float* out) {
    __shared__ float Wsm[Ld * 2 * Hd];
    __shared__ float em[Td * Ld];
    __shared__ float tr[Ld * Ld];
    __shared__ int msk[Td];
    __shared__ int lab[Td];
    __shared__ int lab_is64;
    __shared__ float score_sm;
    __shared__ float logZ_sm;

    const int b = blockIdx.x;
    const int tid = threadIdx.x;

    if (tid == 0) {
        int odd_or = 0;
        for (int i = 1; i < 128; i += 2) odd_or |= labels32[i];
        lab_is64 = (odd_or == 0) ? 1 : 0;
    }
    for (int i = tid; i < Ld * 2 * Hd; i += blockDim.x) Wsm[i] = Wout[i];
    for (int i = tid; i < Td; i += blockDim.x) msk[i] = mask[(size_t)b * Td + i];
    for (int i = tid; i < Ld * Ld; i += blockDim.x) tr[i] = trans[i];
    __syncthreads();
    const int stride = lab_is64 ? 2 : 1;
    for (int i = tid; i < Td; i += blockDim.x)
        lab[i] = labels32[((size_t)b * Td + i) * stride];
    __syncthreads();

    const int w = tid >> 5, lane = tid & 31;
    for (int t = w; t < Td; t += 8) {
        float p[Ld];
#pragma unroll
        for (int l = 0; l < Ld; l++) p[l] = 0.f;
        const __nv_bfloat16* hfh = &g_hb[0][t + 1][0][b][0];
        const __nv_bfloat16* hfl = &g_hb[0][t + 1][1][b][0];
        const __nv_bfloat16* hbh = &g_hb[1][t][0][b][0];
        const __nv_bfloat16* hbl = &g_hb[1][t][1][b][0];
#pragma unroll
        for (int kk = 0; kk < 8; kk++) {
            int k = kk * 32 + lane;
            float hv = __bfloat162float(hfh[k]) + __bfloat162float(hfl[k]);
#pragma unroll
            for (int l = 0; l < Ld; l++) p[l] += hv * Wsm[l * 512 + k];
        }
#pragma unroll
        for (int kk = 0; kk < 8; kk++) {
            int k = kk * 32 + lane;
            float hv = __bfloat162float(hbh[k]) + __bfloat162float(hbl[k]);
#pragma unroll
            for (int l = 0; l < Ld; l++) p[l] += hv * Wsm[l * 512 + 256 + k];
        }
#pragma unroll
        for (int l = 0; l < Ld; l++) {
            float v = p[l];
#pragma unroll
            for (int off = 16; off; off >>= 1) v += __shfl_down_sync(0xffffffffu, v, off);
            if (lane == 0) em[t * Ld + l] = v + bout[l];
        }
    }
    __syncthreads();

    if (tid == 32) {
        int prev = lab[0];
        float sc = start_t[prev] + em[0 * Ld + prev];
        for (int t = 1; t < Td; t++) {
            if (msk[t]) {
                int cur = lab[t];
                sc += em[t * Ld + cur] + tr[prev * Ld + cur];
                prev = cur;
            }
        }
        sc += end_t[prev];
        score_sm = sc;
    }

    if (tid < 32) {
        const int j = lane;
        const bool act = j < Ld;
        float tcol[Ld];
#pragma unroll
        for (int i = 0; i < Ld; i++) tcol[i] = act ? tr[i * Ld + j] : 0.f;
        float alpha = act ? (start_t[j] + em[0 * Ld + j]) : -1e30f;
        for (int t = 1; t < Td; t++) {
            float vv[Ld];
            float mx = -1e30f;
#pragma unroll
            for (int i = 0; i < Ld; i++) {
                float ai = __shfl_sync(0xffffffffu, alpha, i);
                vv[i] = ai + tcol[i];
                mx = fmaxf(mx, vv[i]);
            }
            float ssum = 0.f;
#pragma unroll
            for (int i = 0; i < Ld; i++) ssum += __expf(vv[i] - mx);
            float nxt = mx + __logf(ssum) + (act ? em[t * Ld + j] : 0.f);
            if (msk[t]) alpha = nxt;
        }
        float v = act ? (alpha + end_t[j]) : -1e30f;
        float mx = v;
#pragma unroll
        for (int off = 16; off; off >>= 1) mx = fmaxf(mx, __shfl_xor_sync(0xffffffffu, mx, off));
        float s = __expf(v - mx);
#pragma unroll
        for (int off = 16; off; off >>= 1) s += __shfl_xor_sync(0xffffffffu, s, off);
        if (lane == 0) logZ_sm = mx + __logf(s);
    }
    __syncthreads();
    if (tid == 0) atomicAdd(out, logZ_sm - score_sm);
}

// ---------------- launch ----------------
extern "C" void kernel_launch(void* const* d_in, const int* in_sizes, int n_in,
                              void* d_out, int out_size) {
    const float* X      = (const float*)d_in[0];
    const int*   mask   = (const int*)d_in[1];
    const int*   labels = (const int*)d_in[2];
    const float* Wih_f = (const float*)d_in[3];
    const float* Whh_f = (const float*)d_in[4];
    const float* bih_f = (const float*)d_in[5];
    const float* bhh_f = (const float*)d_in[6];
    const float* Wih_b = (const float*)d_in[7];
    const float* Whh_b = (const float*)d_in[8];
    const float* bih_b = (const float*)d_in[9];
    const float* bhh_b = (const float*)d_in[10];
    const float* W_out = (const float*)d_in[11];
    const float* b_out = (const float*)d_in[12];
    const float* start_t = (const float*)d_in[13];
    const float* end_t   = (const float*)d_in[14];
    const float* trans   = (const float*)d_in[15];
    float* out = (float*)d_out;

    const int gemm_smem = 2 * GSTG * (int)sizeof(__nv_bfloat16);   // 81920
    cudaFuncSetAttribute(gemm_xw_tc, cudaFuncAttributeMaxDynamicSharedMemorySize, gemm_smem);
    cudaFuncSetAttribute(lstm_rec_mma, cudaFuncAttributeMaxDynamicSharedMemorySize, REC_SMEM);

    init_kernel<<<128, 256>>>(out);
    gemm_xw_tc<<<dim3(8, 512, 2), 256, gemm_smem>>>(X, Wih_f, Wih_b,
                                                    bih_f, bhh_f, bih_b, bhh_b);
    lstm_rec_mma<<<32, 256, REC_SMEM>>>(Whh_f, Whh_b);
    emis_crf<<<128, 256>>>(mask, labels, W_out, b_out, start_t, end_t, trans, out);
}

// round 7
// speedup vs baseline: 1.3931x; 1.1325x over previous
#include <cuda_runtime.h>
#include <cuda_bf16.h>
#include <math.h>
#include <stdint.h>

#define Bd 128
#define Td 512
#define Ed 768
#define Hd 256
#define H4 1024
#define Ld 9

// ---------------- device scratch (static, allowed) ----------------
__device__ float g_xw[2][Td][Bd][H4];                       // 536 MB
__device__ __nv_bfloat16 g_hb[2][Td + 1][2][Bd][Hd];        // h hi/lo planes
__device__ unsigned g_bar_count[8];
__device__ unsigned g_bar_gen[8];
__device__ int g_prog[2][4];                                 // gemm quarter counters

// ---------------- init ----------------
__global__ void init_kernel(float* out) {
    int idx = blockIdx.x * blockDim.x + threadIdx.x;   // 32768 threads
    ((uint32_t*)g_hb[0][0])[idx] = 0u;
    ((uint32_t*)g_hb[1][Td])[idx] = 0u;
    if (idx < 8) {
        g_bar_count[idx] = 0u;
        g_bar_gen[idx] = 0u;
        g_prog[idx >> 2][idx & 3] = 0;
    }
    if (idx == 0) out[0] = 0.f;
}

// ---------------- mma helpers ----------------
__device__ __forceinline__ void ldsm4(uint32_t (&r)[4], uint32_t addr) {
    asm volatile("ldmatrix.sync.aligned.m8n8.x4.shared.b16 {%0,%1,%2,%3}, [%4];"
                 : "=r"(r[0]), "=r"(r[1]), "=r"(r[2]), "=r"(r[3]) : "r"(addr));
}
__device__ __forceinline__ void mma_bf16(float (&d)[4], const uint32_t (&a)[4],
                                         uint32_t b0, uint32_t b1) {
    asm volatile(
        "mma.sync.aligned.m16n8k16.row.col.f32.bf16.bf16.f32 "
        "{%0,%1,%2,%3}, {%4,%5,%6,%7}, {%8,%9}, {%0,%1,%2,%3};"
        : "+f"(d[0]), "+f"(d[1]), "+f"(d[2]), "+f"(d[3])
        : "r"(a[0]), "r"(a[1]), "r"(a[2]), "r"(a[3]), "r"(b0), "r"(b1));
}
__device__ __forceinline__ void split4(float4 v, uint32_t& h01, uint32_t& h23,
                                       uint32_t& l01, uint32_t& l23) {
    asm("cvt.rn.bf16x2.f32 %0, %1, %2;" : "=r"(h01) : "f"(v.y), "f"(v.x));
    asm("cvt.rn.bf16x2.f32 %0, %1, %2;" : "=r"(h23) : "f"(v.w), "f"(v.z));
    float r0 = v.x - __uint_as_float(h01 << 16);
    float r1 = v.y - __uint_as_float(h01 & 0xffff0000u);
    float r2 = v.z - __uint_as_float(h23 << 16);
    float r3 = v.w - __uint_as_float(h23 & 0xffff0000u);
    asm("cvt.rn.bf16x2.f32 %0, %1, %2;" : "=r"(l01) : "f"(r1), "f"(r0));
    asm("cvt.rn.bf16x2.f32 %0, %1, %2;" : "=r"(l23) : "f"(r3), "f"(r2));
}
__device__ __forceinline__ void cvt_split_store(float4 v, __nv_bfloat16* hi, __nv_bfloat16* lo) {
    uint32_t h01, h23, l01, l23;
    split4(v, h01, h23, l01, l23);
    *(uint2*)hi = make_uint2(h01, h23);
    *(uint2*)lo = make_uint2(l01, l23);
}
__device__ __forceinline__ void cp16(uint32_t s, const void* g) {
    asm volatile("cp.async.cg.shared.global [%0], [%1], 16;" :: "r"(s), "l"(g));
}
#define CP_COMMIT() asm volatile("cp.async.commit_group;" ::: "memory")
#define CP_WAIT0()  asm volatile("cp.async.wait_group 0;" :: : "memory")

// ---------------- GEMM tile body (R6-proven, parameterized) ----------------
#define GSTG 20480           // bf16 elements per stage
#define GPLN 5120            // bf16 elements per plane (128*40)

__device__ void gemm_tile(const float* __restrict__ X, const float* __restrict__ W,
                          const float* __restrict__ bih, const float* __restrict__ bhh,
                          int dir, int m0, int n0, __nv_bfloat16* smbf, int tid) {
    const int lane = tid & 31;
    const int warp = tid >> 5;
    const int wm = (warp >> 1) << 5;
    const int wn = (warp & 1) << 6;

    const uint32_t smem_base = (uint32_t)__cvta_generic_to_shared(smbf);

    int lrow[4], lcol[4];
    const float *Ag[4], *Bg[4];
#pragma unroll
    for (int i = 0; i < 4; i++) {
        int idx = tid + i * 256;
        lrow[i] = idx >> 3;
        lcol[i] = (idx & 7) * 4;
        Ag[i] = X + (size_t)(m0 + lrow[i]) * Ed + lcol[i];
        Bg[i] = W + (size_t)(n0 + lrow[i]) * Ed + lcol[i];
    }

    float4 ra[4], rb[4];
#pragma unroll
    for (int i = 0; i < 4; i++) {
        ra[i] = *(const float4*)(Ag[i]);
        rb[i] = *(const float4*)(Bg[i]);
    }
#pragma unroll
    for (int i = 0; i < 4; i++) {
        int off = lrow[i] * 40 + lcol[i];
        cvt_split_store(ra[i], &smbf[off], &smbf[off + GPLN]);
        cvt_split_store(rb[i], &smbf[off + 2 * GPLN], &smbf[off + 3 * GPLN]);
    }
    __syncthreads();

    float acc[2][8][4];
#pragma unroll
    for (int i = 0; i < 2; i++)
#pragma unroll
        for (int j = 0; j < 8; j++)
#pragma unroll
            for (int q = 0; q < 4; q++) acc[i][j][q] = 0.f;

    int stage = 0;
#pragma unroll 1
    for (int k0 = 0; k0 < Ed; k0 += 32) {
        const bool more = (k0 + 32) < Ed;
        if (more) {
#pragma unroll
            for (int i = 0; i < 4; i++) {
                ra[i] = *(const float4*)(Ag[i] + k0 + 32);
                rb[i] = *(const float4*)(Bg[i] + k0 + 32);
            }
        }

        const uint32_t so = stage * GSTG;
#pragma unroll
        for (int ks = 0; ks < 32; ks += 16) {
            uint32_t ah[2][4], al[2][4];
            const int arow = lane & 15;
            const int acol = ks + ((lane >> 4) << 3);
#pragma unroll
            for (int i = 0; i < 2; i++) {
                uint32_t aoff = so + (uint32_t)((wm + i * 16 + arow) * 40 + acol);
                ldsm4(ah[i], smem_base + aoff * 2);
                ldsm4(al[i], smem_base + (aoff + GPLN) * 2);
            }
            const int brow = ((lane >> 4) << 3) + (lane & 7);
            const int bcol = ks + (((lane >> 3) & 1) << 3);
#pragma unroll
            for (int g = 0; g < 4; g++) {
                uint32_t boff = so + 2 * GPLN + (uint32_t)((wn + g * 16 + brow) * 40 + bcol);
                uint32_t bh[4], bl[4];
                ldsm4(bh, smem_base + boff * 2);
                ldsm4(bl, smem_base + (boff + GPLN) * 2);
#pragma unroll
                for (int i = 0; i < 2; i++) {
                    mma_bf16(acc[i][2 * g],     ah[i], bh[0], bh[1]);
                    mma_bf16(acc[i][2 * g],     ah[i], bl[0], bl[1]);
                    mma_bf16(acc[i][2 * g],     al[i], bh[0], bh[1]);
                    mma_bf16(acc[i][2 * g + 1], ah[i], bh[2], bh[3]);
                    mma_bf16(acc[i][2 * g + 1], ah[i], bl[2], bl[3]);
                    mma_bf16(acc[i][2 * g + 1], al[i], bh[2], bh[3]);
                }
            }
        }

        if (more) {
            const int ns = stage ^ 1;
#pragma unroll
            for (int i = 0; i < 4; i++) {
                int off = ns * GSTG + lrow[i] * 40 + lcol[i];
                cvt_split_store(ra[i], &smbf[off], &smbf[off + GPLN]);
                cvt_split_store(rb[i], &smbf[off + 2 * GPLN], &smbf[off + 3 * GPLN]);
            }
            __syncthreads();
            stage = ns;
        }
    }

    const int lr = lane >> 2;
    const int lc = (lane & 3) * 2;
#pragma unroll
    for (int j = 0; j < 8; j++) {
        const int n = n0 + wn + j * 8 + lc;
        const float b0 = bih[n] + bhh[n];
        const float b1 = bih[n + 1] + bhh[n + 1];
#pragma unroll
        for (int i = 0; i < 2; i++) {
            int m = m0 + wm + i * 16 + lr;
            int bb = m >> 9, t = m & 511;
            *(float2*)&g_xw[dir][t][bb][n] =
                make_float2(acc[i][j][0] + b0, acc[i][j][1] + b1);
            m += 8; bb = m >> 9; t = m & 511;
            *(float2*)&g_xw[dir][t][bb][n] =
                make_float2(acc[i][j][2] + b0, acc[i][j][3] + b1);
        }
    }
    // make this tile's stores visible, then count it (one add per CTA)
    __threadfence();
    __syncthreads();
}

// ---------------- recurrence smem layout ----------------
#define RST 528
#define WHI_OFF 0
#define WLO_OFF (64 * RST)
#define HHI_OFF (2 * 64 * RST)
#define HLO_OFF (2 * 64 * RST + 128 * RST)
#define REC_SMEM (2 * 64 * RST + 2 * 128 * RST)   // 202752

__device__ __forceinline__ float sigf(float x) { return 1.f / (1.f + __expf(-x)); }

// ---------------- fused persistent kernel ----------------
__global__ void __launch_bounds__(256, 1)
fused_gemm_rec(const float* __restrict__ X,
               const float* __restrict__ Wf, const float* __restrict__ Wb,
               const float* __restrict__ bihf, const float* __restrict__ bhhf,
               const float* __restrict__ bihb, const float* __restrict__ bhhb,
               const float* __restrict__ Whhf, const float* __restrict__ Whhb) {
    extern __shared__ char fsm[];
    const int tid = threadIdx.x;
    const int bx = blockIdx.x;

    if (bx >= 32) {
        // ---------------- GEMM workers ----------------
        __nv_bfloat16* smbf = (__nv_bfloat16*)fsm;
        const int workers = gridDim.x - 32;
        const int wix = bx - 32;
#pragma unroll 1
        for (int g = wix; g < 8192; g += workers) {
            const int phase = g >> 11;
            const int r = g & 2047;
            const int dir = r >> 10;
            const int q = dir ? (3 - phase) : phase;
            const int idx = r & 1023;
            const int bb = idx >> 3;
            const int nt = idx & 7;
            gemm_tile(X, dir ? Wb : Wf, dir ? bihb : bihf, dir ? bhhb : bhhf,
                      dir, (bb * 4 + q) * 128, nt * 128, smbf, tid);
            if (tid == 0) atomicAdd(&g_prog[dir][q], 1);
            __syncthreads();
        }
        return;
    }

    // ---------------- recurrence (R6-proven) ----------------
    const uint32_t sb = (uint32_t)__cvta_generic_to_shared(fsm);
    const int warp = tid >> 5;
    const int lane = tid & 31;
    const int dir  = bx >> 4;
    const int j0   = (bx & 15) * 16;
    const int grp  = dir;

    const float* __restrict__ Whh = dir ? Whhb : Whhf;

#pragma unroll
    for (int i = 0; i < 16; i++) {
        int idx = tid + i * 256;
        int r = idx >> 6;
        int k4 = (idx & 63) * 4;
        int g = r >> 4, jj = r & 15;
        float4 v = *(const float4*)&Whh[(size_t)(g * Hd + j0 + jj) * Hd + k4];
        uint32_t h01, h23, l01, l23;
        split4(v, h01, h23, l01, l23);
        uint32_t off = (uint32_t)(r * RST + k4 * 2);
        asm volatile("st.shared.v2.b32 [%0], {%1,%2};"
                     :: "r"(sb + WHI_OFF + off), "r"(h01), "r"(h23) : "memory");
        asm volatile("st.shared.v2.b32 [%0], {%1,%2};"
                     :: "r"(sb + WLO_OFF + off), "r"(l01), "r"(l23) : "memory");
    }
    __syncthreads();

    const int lr = lane >> 2;
    const int c0 = (lane & 3) * 2;
    const int b0 = warp * 16 + lr;
    const int arow = warp * 16 + (lane & 15);
    const int ac_l = lane >> 4;
    const int brow = ((lane >> 4) << 3) + (lane & 7);
    const int bc_l = (lane >> 3) & 1;

    float cst[8];
#pragma unroll
    for (int i = 0; i < 8; i++) cst[i] = 0.f;

#pragma unroll 1
    for (int s = 0; s < Td; s++) {
        const int t     = dir ? (Td - 1 - s) : s;
        const int rslot = dir ? (t + 1) : t;
        const int wslot = dir ? t : (t + 1);

        // gate on gemm progress at quarter boundaries
        if ((s & 127) == 0) {
            const int q = dir ? (3 - (s >> 7)) : (s >> 7);
            if (tid == 0) {
                while (*(volatile int*)&g_prog[dir][q] < 1024) { __nanosleep(128); }
            }
            __syncthreads();
            __threadfence();
        }

        float acc[8][4];
#pragma unroll
        for (int nt = 0; nt < 8; nt++) {
            int g = nt >> 1;
            int jc = g * Hd + j0 + (nt & 1) * 8 + c0;
            float2 va = *(const float2*)&g_xw[dir][t][b0][jc];
            float2 vb = *(const float2*)&g_xw[dir][t][b0 + 8][jc];
            acc[nt][0] = va.x; acc[nt][1] = va.y;
            acc[nt][2] = vb.x; acc[nt][3] = vb.y;
        }

        const char* hi_src = (const char*)&g_hb[dir][rslot][0][0][0];
        const char* lo_src = (const char*)&g_hb[dir][rslot][1][0][0];
#pragma unroll
        for (int i = 0; i < 16; i++) {
            int idx = tid + i * 256;
            int row = idx >> 5, ch = idx & 31;
            uint32_t d = (uint32_t)(row * RST + ch * 16);
            int srcoff = row * 512 + ch * 16;
            cp16(sb + HHI_OFF + d, hi_src + srcoff);
            cp16(sb + HLO_OFF + d, lo_src + srcoff);
        }
        CP_COMMIT();
        CP_WAIT0();
        __syncthreads();

#pragma unroll
        for (int ks = 0; ks < 16; ks++) {
            uint32_t ah[4], al[4];
            uint32_t aaddr = sb + HHI_OFF + (uint32_t)(arow * RST + (ks * 2 + ac_l) * 16);
            ldsm4(ah, aaddr);
            ldsm4(al, aaddr + (HLO_OFF - HHI_OFF));
#pragma unroll
            for (int g2 = 0; g2 < 4; g2++) {
                uint32_t bh[4], bl[4];
                uint32_t baddr = sb + WHI_OFF +
                    (uint32_t)((g2 * 16 + brow) * RST + (ks * 2 + bc_l) * 16);
                ldsm4(bh, baddr);
                ldsm4(bl, baddr + WLO_OFF);
                mma_bf16(acc[2 * g2],     ah, bh[0], bh[1]);
                mma_bf16(acc[2 * g2],     al, bh[0], bh[1]);
                mma_bf16(acc[2 * g2],     ah, bl[0], bl[1]);
                mma_bf16(acc[2 * g2 + 1], ah, bh[2], bh[3]);
                mma_bf16(acc[2 * g2 + 1], al, bh[2], bh[3]);
                mma_bf16(acc[2 * g2 + 1], ah, bl[2], bl[3]);
            }
        }

#pragma unroll
        for (int m = 0; m < 2; m++) {
            const int b = b0 + m * 8;
#pragma unroll
            for (int jh = 0; jh < 2; jh++) {
                float hv[2];
#pragma unroll
                for (int c = 0; c < 2; c++) {
                    int q = m * 2 + c;
                    float iv = acc[jh + 0][q];
                    float fv = acc[jh + 2][q];
                    float gv = acc[jh + 4][q];
                    float ov = acc[jh + 6][q];
                    float cc = cst[m * 4 + jh * 2 + c];
                    cc = sigf(fv) * cc + sigf(iv) * tanhf(gv);
                    cst[m * 4 + jh * 2 + c] = cc;
                    hv[c] = sigf(ov) * tanhf(cc);
                }
                uint32_t h2, l2;
                asm("cvt.rn.bf16x2.f32 %0, %1, %2;" : "=r"(h2) : "f"(hv[1]), "f"(hv[0]));
                float r0 = hv[0] - __uint_as_float(h2 << 16);
                float r1 = hv[1] - __uint_as_float(h2 & 0xffff0000u);
                asm("cvt.rn.bf16x2.f32 %0, %1, %2;" : "=r"(l2) : "f"(r1), "f"(r0));
                const int jc = j0 + jh * 8 + c0;
                *(uint32_t*)&g_hb[dir][wslot][0][b][jc] = h2;
                *(uint32_t*)&g_hb[dir][wslot][1][b][jc] = l2;
            }
        }

        __threadfence();
        __syncthreads();
        if (tid == 0) {
            unsigned arr = atomicAdd(&g_bar_count[grp], 1u);
            if (arr == 15u) {
                g_bar_count[grp] = 0u;
                __threadfence();
                atomicAdd(&g_bar_gen[grp], 1u);
            } else {
                while (*((volatile unsigned*)&g_bar_gen[grp]) < (unsigned)(s + 1))
                    __nanosleep(64);
                __threadfence();
            }
        }
        __syncthreads();
    }
}

// ---------------- emissions + CRF NLL (unchanged, proven) ----------------
__global__ void emis_crf(const int* __restrict__ mask, const int* __restrict__ labels32,
                         const float* __restrict__ Wout, const float* __restrict__ bout,
                         const float* __restrict__ start_t, const float* __restrict__ end_t,
                         const float* __restrict__ trans, float* out) {
    __shared__ float Wsm[Ld * 2 * Hd];
    __shared__ float em[Td * Ld];
    __shared__ float tr[Ld * Ld];
    __shared__ int msk[Td];
    __shared__ int lab[Td];
    __shared__ int lab_is64;
    __shared__ float score_sm;
    __shared__ float logZ_sm;

    const int b = blockIdx.x;
    const int tid = threadIdx.x;

    if (tid == 0) {
        int odd_or = 0;
        for (int i = 1; i < 128; i += 2) odd_or |= labels32[i];
        lab_is64 = (odd_or == 0) ? 1 : 0;
    }
    for (int i = tid; i < Ld * 2 * Hd; i += blockDim.x) Wsm[i] = Wout[i];
    for (int i = tid; i < Td; i += blockDim.x) msk[i] = mask[(size_t)b * Td + i];
    for (int i = tid; i < Ld * Ld; i += blockDim.x) tr[i] = trans[i];
    __syncthreads();
    const int stride = lab_is64 ? 2 : 1;
    for (int i = tid; i < Td; i += blockDim.x)
        lab[i] = labels32[((size_t)b * Td + i) * stride];
    __syncthreads();

    const int w = tid >> 5, lane = tid & 31;
    for (int t = w; t < Td; t += 8) {
        float p[Ld];
#pragma unroll
        for (int l = 0; l < Ld; l++) p[l] = 0.f;
        const __nv_bfloat16* hfh = &g_hb[0][t + 1][0][b][0];
        const __nv_bfloat16* hfl = &g_hb[0][t + 1][1][b][0];
        const __nv_bfloat16* hbh = &g_hb[1][t][0][b][0];
        const __nv_bfloat16* hbl = &g_hb[1][t][1][b][0];
#pragma unroll
        for (int kk = 0; kk < 8; kk++) {
            int k = kk * 32 + lane;
            float hv = __bfloat162float(hfh[k]) + __bfloat162float(hfl[k]);
#pragma unroll
            for (int l = 0; l < Ld; l++) p[l] += hv * Wsm[l * 512 + k];
        }
#pragma unroll
        for (int kk = 0; kk < 8; kk++) {
            int k = kk * 32 + lane;
            float hv = __bfloat162float(hbh[k]) + __bfloat162float(hbl[k]);
#pragma unroll
            for (int l = 0; l < Ld; l++) p[l] += hv * Wsm[l * 512 + 256 + k];
        }
#pragma unroll
        for (int l = 0; l < Ld; l++) {
            float v = p[l];
#pragma unroll
            for (int off = 16; off; off >>= 1) v += __shfl_down_sync(0xffffffffu, v, off);
            if (lane == 0) em[t * Ld + l] = v + bout[l];
        }
    }
    __syncthreads();

    if (tid == 32) {
        int prev = lab[0];
        float sc = start_t[prev] + em[0 * Ld + prev];
        for (int t = 1; t < Td; t++) {
            if (msk[t]) {
                int cur = lab[t];
                sc += em[t * Ld + cur] + tr[prev * Ld + cur];
                prev = cur;
            }
        }
        sc += end_t[prev];
        score_sm = sc;
    }

    if (tid < 32) {
        const int j = lane;
        const bool act = j < Ld;
        float tcol[Ld];
#pragma unroll
        for (int i = 0; i < Ld; i++) tcol[i] = act ? tr[i * Ld + j] : 0.f;
        float alpha = act ? (start_t[j] + em[0 * Ld + j]) : -1e30f;
        for (int t = 1; t < Td; t++) {
            float vv[Ld];
            float mx = -1e30f;
#pragma unroll
            for (int i = 0; i < Ld; i++) {
                float ai = __shfl_sync(0xffffffffu, alpha, i);
                vv[i] = ai + tcol[i];
                mx = fmaxf(mx, vv[i]);
            }
            float ssum = 0.f;
#pragma unroll
            for (int i = 0; i < Ld; i++) ssum += __expf(vv[i] - mx);
            float nxt = mx + __logf(ssum) + (act ? em[t * Ld + j] : 0.f);
            if (msk[t]) alpha = nxt;
        }
        float v = act ? (alpha + end_t[j]) : -1e30f;
        float mx = v;
#pragma unroll
        for (int off = 16; off; off >>= 1) mx = fmaxf(mx, __shfl_xor_sync(0xffffffffu, mx, off));
        float s = __expf(v - mx);
#pragma unroll
        for (int off = 16; off; off >>= 1) s += __shfl_xor_sync(0xffffffffu, s, off);
        if (lane == 0) logZ_sm = mx + __logf(s);
    }
    __syncthreads();
    if (tid == 0) atomicAdd(out, logZ_sm - score_sm);
}

// ---------------- launch ----------------
extern "C" void kernel_launch(void* const* d_in, const int* in_sizes, int n_in,
                              void* d_out, int out_size) {
    const float* X      = (const float*)d_in[0];
    const int*   mask   = (const int*)d_in[1];
    const int*   labels = (const int*)d_in[2];
    const float* Wih_f = (const float*)d_in[3];
    const float* Whh_f = (const float*)d_in[4];
    const float* bih_f = (const float*)d_in[5];
    const float* bhh_f = (const float*)d_in[6];
    const float* Wih_b = (const float*)d_in[7];
    const float* Whh_b = (const float*)d_in[8];
    const float* bih_b = (const float*)d_in[9];
    const float* bhh_b = (const float*)d_in[10];
    const float* W_out = (const float*)d_in[11];
    const float* b_out = (const float*)d_in[12];
    const float* start_t = (const float*)d_in[13];
    const float* end_t   = (const float*)d_in[14];
    const float* trans   = (const float*)d_in[15];
    float* out = (float*)d_out;

    static int nsm = 0;
    if (nsm == 0) {
        cudaDeviceGetAttribute(&nsm, cudaDevAttrMultiProcessorCount, 0);
        if (nsm < 64) nsm = 64;          // safety floor
        cudaFuncSetAttribute(fused_gemm_rec,
                             cudaFuncAttributeMaxDynamicSharedMemorySize, REC_SMEM);
    }

    init_kernel<<<128, 256>>>(out);
    fused_gemm_rec<<<nsm, 256, REC_SMEM>>>(X, Wih_f, Wih_b,
                                           bih_f, bhh_f, bih_b, bhh_b,
                                           Whh_f, Whh_b);
    emis_crf<<<128, 256>>>(mask, labels, W_out, b_out, start_t, end_t, trans, out);
}